// round 6
// baseline (speedup 1.0000x reference)
#include <cuda_runtime.h>
#include <cstdint>
#include <cstddef>

// ===================== problem constants =====================
constexpr int C    = 128;            // channels
constexpr int NET  = 7;              // edge types
constexpr int NMAX = 100000;
constexpr int NSEGMAX = NMAX * NET;  // 700000
constexpr int EMAX = 700000;

// ===================== device scratch ========================
__device__ unsigned g_cnt[NSEGMAX];             // segment counts
__device__ unsigned g_off[NSEGMAX + 1];         // CSR offsets
__device__ unsigned g_cur[NSEGMAX];             // fill cursors
__device__ int      g_elist[EMAX];              // col index per CSR slot
__device__ unsigned g_bsum[1024];               // scan block sums
__device__ float    g_stats[2 * C];
__device__ float    g_scale[C];
__device__ float    g_shift[C];

// ===================== helpers ===============================
__device__ __forceinline__ uint32_t tf32_rna(float f) {
    uint32_t r;
    asm("cvt.rna.tf32.f32 %0, %1;" : "=r"(r) : "f"(f));
    return r;
}
__device__ __forceinline__ void mma_tf32(float* d, const uint32_t* a, uint32_t b0, uint32_t b1) {
    asm volatile(
        "mma.sync.aligned.m16n8k8.row.col.f32.tf32.tf32.f32 "
        "{%0,%1,%2,%3}, {%4,%5,%6,%7}, {%8,%9}, {%0,%1,%2,%3};"
        : "+f"(d[0]), "+f"(d[1]), "+f"(d[2]), "+f"(d[3])
        : "r"(a[0]), "r"(a[1]), "r"(a[2]), "r"(a[3]), "r"(b0), "r"(b1));
}

// block-wide inclusive scan (blockDim.x = 1024)
__device__ unsigned block_incl_scan(unsigned v, unsigned* wsum) {
    int lane = threadIdx.x & 31, wid = threadIdx.x >> 5;
#pragma unroll
    for (int d = 1; d < 32; d <<= 1) {
        unsigned n = __shfl_up_sync(0xffffffff, v, d);
        if (lane >= d) v += n;
    }
    if (lane == 31) wsum[wid] = v;
    __syncthreads();
    if (wid == 0) {
        unsigned w = wsum[lane];
#pragma unroll
        for (int d = 1; d < 32; d <<= 1) {
            unsigned n = __shfl_up_sync(0xffffffff, w, d);
            if (lane >= d) w += n;
        }
        wsum[lane] = w;
    }
    __syncthreads();
    return v + (wid > 0 ? wsum[wid - 1] : 0u);
}

// ===================== CSR build =============================
__global__ void zero_kernel(int nseg) {
    int i = blockIdx.x * blockDim.x + threadIdx.x;
    int stride = gridDim.x * blockDim.x;
    for (int j = i; j < nseg; j += stride) g_cnt[j] = 0u;
    if (i < 2 * C) g_stats[i] = 0.f;
}

__global__ void count_kernel(const int* __restrict__ row,
                             const int* __restrict__ et, int E) {
    int e = blockIdx.x * blockDim.x + threadIdx.x;
    if (e >= E) return;
    int t = et[e];
    if (t == NET - 1) return;
    atomicAdd(&g_cnt[row[e] * NET + t], 1u);
}

__global__ void __launch_bounds__(1024) scan1_kernel(int nseg) {
    __shared__ unsigned wsum[32];
    int i = blockIdx.x * 1024 + threadIdx.x;
    unsigned v = (i < nseg) ? g_cnt[i] : 0u;
    unsigned incl = block_incl_scan(v, wsum);
    if (i < nseg) g_off[i] = incl - v;
    if (threadIdx.x == 1023) g_bsum[blockIdx.x] = incl;
}
__global__ void __launch_bounds__(1024) scan2_kernel(int nblocks, int nseg) {
    __shared__ unsigned wsum[32];
    int t = threadIdx.x;
    unsigned v = (t < nblocks) ? g_bsum[t] : 0u;
    unsigned incl = block_incl_scan(v, wsum);
    if (t < nblocks) g_bsum[t] = incl - v;
    if (t == nblocks - 1) g_off[nseg] = incl;
}
__global__ void __launch_bounds__(1024) scan3_kernel(int nseg) {
    int i = blockIdx.x * 1024 + threadIdx.x;
    if (i >= nseg) return;
    unsigned o = g_off[i] + g_bsum[blockIdx.x];
    g_off[i] = o;
    g_cur[i] = o;
}

__global__ void fill_kernel(const int* __restrict__ row,
                            const int* __restrict__ col,
                            const int* __restrict__ et, int E) {
    int e = blockIdx.x * blockDim.x + threadIdx.x;
    if (e >= E) return;
    int t = et[e];
    if (t == NET - 1) return;
    int seg = row[e] * NET + t;
    unsigned pos = atomicAdd(&g_cur[seg], 1u);
    g_elist[pos] = col[e];
}

// ===================== fused aggregate + GEMM + stats ========
// CTA: 128 output rows, 512 threads (16 warps, 4x4 warp grid of 32x32 tiles).
// Loop t = 0..6: load W_t into Bs, gather-mean type-t neighborhood of x into
// As (t=6 -> self row x), MMA-accumulate 128x128x128 into registers.
// Epilogue: write out once + fused BN column stats.
constexpr int AS_STRIDE = 132;   // bank = 4*row + k : conflict-free frag loads
constexpr int BS_STRIDE = 136;   // bank = 8*k + n   : conflict-free frag loads
constexpr int SMEM_A_FLOATS = 128 * AS_STRIDE;   // 16896
constexpr int SMEM_B_FLOATS = 128 * BS_STRIDE;   // 17408
constexpr size_t FUSED_SMEM = (size_t)(SMEM_A_FLOATS + SMEM_B_FLOATS + 2 * C) * 4;  // 138240 B

__global__ void __launch_bounds__(512, 1)
fused_kernel(const float* __restrict__ x, const float* __restrict__ w,
             float* __restrict__ out, int nrows) {
    extern __shared__ float sm[];
    float* As = sm;                                   // [128][132] tf32 bits
    float* Bs = sm + SMEM_A_FLOATS;                   // [128][136] tf32 bits
    float* sstat = sm + SMEM_A_FLOATS + SMEM_B_FLOATS;// [256] col sums / sumsq

    const int tid = threadIdx.x;
    const int wid = tid >> 5, lane = tid & 31;
    const int m0 = blockIdx.x * 128;
    const float4* x4 = reinterpret_cast<const float4*>(x);

    if (tid < 2 * C) sstat[tid] = 0.f;

    const int wm = (wid >> 2) * 32;      // warp M offset
    const int wn = (wid & 3) * 32;       // warp N offset
    const int gr = lane >> 2, gc = lane & 3;

    float acc[2][4][4];
#pragma unroll
    for (int f = 0; f < 2; ++f)
#pragma unroll
        for (int g = 0; g < 4; ++g)
#pragma unroll
            for (int q = 0; q < 4; ++q) acc[f][g][q] = 0.f;

    const uint32_t* Au = reinterpret_cast<const uint32_t*>(As);
    const uint32_t* Bu = reinterpret_cast<const uint32_t*>(Bs);

    for (int t = 0; t < NET; ++t) {
        // ---- load B_t = W[t*128 .. t*128+127][0..127] into Bs (tf32) ----
#pragma unroll
        for (int i = 0; i < 8; ++i) {
            int e = tid + i * 512;                    // 0..4095
            int r = e >> 5, c4 = e & 31;
            float4 v = *reinterpret_cast<const float4*>(&w[(size_t)(t * C + r) * C + c4 * 4]);
            uint32_t* dst = reinterpret_cast<uint32_t*>(&Bs[r * BS_STRIDE + c4 * 4]);
            dst[0] = tf32_rna(v.x); dst[1] = tf32_rna(v.y);
            dst[2] = tf32_rna(v.z); dst[3] = tf32_rna(v.w);
        }
        // ---- aggregate: warp-per-row, 8 rows per warp ----
#pragma unroll
        for (int i = 0; i < 8; ++i) {
            int r = wid * 8 + i;
            int gn = m0 + r;
            float4 val = make_float4(0.f, 0.f, 0.f, 0.f);
            if (gn < nrows) {
                if (t == NET - 1) {
                    val = x4[(size_t)gn * 32 + lane];          // self slot
                } else {
                    int seg = gn * NET + t;
                    unsigned beg = g_off[seg], end = g_off[seg + 1];
                    if (end > beg) {
                        float4 s = make_float4(0.f, 0.f, 0.f, 0.f);
                        for (unsigned e = beg; e < end; ++e) {
                            int c = g_elist[e];
                            float4 v = x4[(size_t)c * 32 + lane];
                            s.x += v.x; s.y += v.y; s.z += v.z; s.w += v.w;
                        }
                        float inv = 1.0f / (float)(end - beg);
                        val = make_float4(s.x * inv, s.y * inv, s.z * inv, s.w * inv);
                    }
                }
            }
            uint32_t* dst = reinterpret_cast<uint32_t*>(&As[r * AS_STRIDE + lane * 4]);
            dst[0] = tf32_rna(val.x); dst[1] = tf32_rna(val.y);
            dst[2] = tf32_rna(val.z); dst[3] = tf32_rna(val.w);
        }
        __syncthreads();
        // ---- MMA accumulate over K=128 ----
#pragma unroll
        for (int k0 = 0; k0 < 128; k0 += 8) {
            uint32_t a[2][4];
#pragma unroll
            for (int f = 0; f < 2; ++f) {
                const uint32_t* ap = &Au[(wm + 16 * f + gr) * AS_STRIDE + k0 + gc];
                a[f][0] = ap[0];
                a[f][1] = ap[8 * AS_STRIDE];
                a[f][2] = ap[4];
                a[f][3] = ap[8 * AS_STRIDE + 4];
            }
#pragma unroll
            for (int g = 0; g < 4; ++g) {
                const uint32_t* bp = &Bu[(k0 + gc) * BS_STRIDE + wn + 8 * g + gr];
                uint32_t b0 = bp[0];
                uint32_t b1 = bp[4 * BS_STRIDE];
#pragma unroll
                for (int f = 0; f < 2; ++f)
                    mma_tf32(acc[f][g], a[f], b0, b1);
            }
        }
        __syncthreads();   // before next t overwrites As/Bs
    }

    // ---- epilogue: write out + fused BN stats ----
#pragma unroll
    for (int f = 0; f < 2; ++f) {
        int r0 = m0 + wm + 16 * f + gr;
#pragma unroll
        for (int g = 0; g < 4; ++g) {
            int cn = wn + 8 * g + gc * 2;
            float s0 = 0.f, q0 = 0.f, s1 = 0.f, q1 = 0.f;
            if (r0 < nrows) {
                float v0 = acc[f][g][0], v1 = acc[f][g][1];
                *reinterpret_cast<float2*>(&out[(size_t)r0 * C + cn]) = make_float2(v0, v1);
                s0 += v0; q0 += v0 * v0; s1 += v1; q1 += v1 * v1;
            }
            if (r0 + 8 < nrows) {
                float v0 = acc[f][g][2], v1 = acc[f][g][3];
                *reinterpret_cast<float2*>(&out[(size_t)(r0 + 8) * C + cn]) = make_float2(v0, v1);
                s0 += v0; q0 += v0 * v0; s1 += v1; q1 += v1 * v1;
            }
            atomicAdd(&sstat[cn], s0);
            atomicAdd(&sstat[C + cn], q0);
            atomicAdd(&sstat[cn + 1], s1);
            atomicAdd(&sstat[C + cn + 1], q1);
        }
    }
    __syncthreads();
    if (tid < 2 * C) atomicAdd(&g_stats[tid], sstat[tid]);
}

// ===================== BN finalize + normalize ===============
__global__ void bnfin_kernel(const float* __restrict__ gamma, const float* __restrict__ beta,
                             float inv_n) {
    int c = threadIdx.x;
    float mean = g_stats[c] * inv_n;
    float var  = g_stats[C + c] * inv_n - mean * mean;
    float sc   = gamma[c] * rsqrtf(var + 1e-5f);
    g_scale[c] = sc;
    g_shift[c] = beta[c] - mean * sc;
}

__global__ void norm_kernel(float* __restrict__ out, size_t n4) {
    size_t i = (size_t)blockIdx.x * blockDim.x + threadIdx.x;
    size_t stride = (size_t)gridDim.x * blockDim.x;
    const float4* sc4 = reinterpret_cast<const float4*>(g_scale);
    const float4* sh4 = reinterpret_cast<const float4*>(g_shift);
    float4* o4 = reinterpret_cast<float4*>(out);
    for (size_t j = i; j < n4; j += stride) {
        int c4 = (int)(j & 31);
        float4 v = o4[j];
        float4 a = sc4[c4], b = sh4[c4];
        v.x = v.x * a.x + b.x;
        v.y = v.y * a.y + b.y;
        v.z = v.z * a.z + b.z;
        v.w = v.w * a.w + b.w;
        o4[j] = v;
    }
}

// ===================== launch ================================
extern "C" void kernel_launch(void* const* d_in, const int* in_sizes, int n_in,
                              void* d_out, int out_size) {
    const float* x     = (const float*)d_in[0];
    const int*   row   = (const int*)d_in[1];   // JAX default x64-disabled: int32
    const int*   col   = (const int*)d_in[2];
    const int*   et    = (const int*)d_in[3];
    const float* w     = (const float*)d_in[4];
    const float* gamma = (const float*)d_in[5];
    const float* beta  = (const float*)d_in[6];
    float* out = (float*)d_out;

    int nrows = in_sizes[0] / C;          // 100000
    int E     = in_sizes[1];              // 700000
    int nseg  = nrows * NET;
    int nblk  = (nseg + 1023) / 1024;

    cudaFuncSetAttribute(fused_kernel, cudaFuncAttributeMaxDynamicSharedMemorySize,
                         (int)FUSED_SMEM);

    zero_kernel<<<512, 256>>>(nseg);
    count_kernel<<<(E + 255) / 256, 256>>>(row, et, E);
    scan1_kernel<<<nblk, 1024>>>(nseg);
    scan2_kernel<<<1, 1024>>>(nblk, nseg);
    scan3_kernel<<<nblk, 1024>>>(nseg);
    fill_kernel<<<(E + 255) / 256, 256>>>(row, col, et, E);
    fused_kernel<<<(nrows + 127) / 128, 512, FUSED_SMEM>>>(x, w, out, nrows);
    bnfin_kernel<<<1, 128>>>(gamma, beta, 1.0f / (float)nrows);
    norm_kernel<<<2048, 256>>>(out, (size_t)nrows * 32);
}

// round 7
// speedup vs baseline: 1.2623x; 1.2623x over previous
#include <cuda_runtime.h>
#include <cuda_fp16.h>
#include <cstdint>
#include <cstddef>

// ===================== problem constants =====================
constexpr int C    = 128;            // channels
constexpr int NET  = 7;              // edge types
constexpr int NMAX = 100000;
constexpr int NSEGMAX = NMAX * NET;  // 700000
constexpr int EMAX = 700000;
constexpr int SCAN_BLK = 1024;

// ===================== device scratch ========================
__device__ unsigned g_cnt[NSEGMAX];             // segment counts (zero-init; re-zeroed at tail)
__device__ unsigned g_off[NSEGMAX + 1];         // CSR offsets
__device__ unsigned g_cur[NSEGMAX];             // fill cursors
__device__ int      g_elist[EMAX];              // col index per CSR slot
__device__ unsigned g_ticket;                   // scan block ticket (zero-init; re-zeroed)
__device__ unsigned long long g_state[1024];    // scan lookback state (zero-init; re-zeroed)
__device__ float    g_stats[2 * C];             // col sums / sumsq (zero-init; re-zeroed)
__device__ float    g_scale[C];
__device__ float    g_shift[C];

// ===================== helpers ===============================
__device__ __forceinline__ uint32_t pack_h2(float a, float b) {
    __half2 h = __floats2half2_rn(a, b);
    return *reinterpret_cast<uint32_t*>(&h);
}
__device__ __forceinline__ void mma_f16(float* d, const uint32_t* a, uint32_t b0, uint32_t b1) {
    asm volatile(
        "mma.sync.aligned.m16n8k16.row.col.f32.f16.f16.f32 "
        "{%0,%1,%2,%3}, {%4,%5,%6,%7}, {%8,%9}, {%0,%1,%2,%3};"
        : "+f"(d[0]), "+f"(d[1]), "+f"(d[2]), "+f"(d[3])
        : "r"(a[0]), "r"(a[1]), "r"(a[2]), "r"(a[3]), "r"(b0), "r"(b1));
}

__device__ unsigned block_incl_scan(unsigned v, unsigned* wsum) {
    int lane = threadIdx.x & 31, wid = threadIdx.x >> 5;
#pragma unroll
    for (int d = 1; d < 32; d <<= 1) {
        unsigned n = __shfl_up_sync(0xffffffff, v, d);
        if (lane >= d) v += n;
    }
    if (lane == 31) wsum[wid] = v;
    __syncthreads();
    if (wid == 0) {
        unsigned w = wsum[lane];
#pragma unroll
        for (int d = 1; d < 32; d <<= 1) {
            unsigned n = __shfl_up_sync(0xffffffff, w, d);
            if (lane >= d) w += n;
        }
        wsum[lane] = w;
    }
    __syncthreads();
    return v + (wid > 0 ? wsum[wid - 1] : 0u);
}

// ===================== CSR build =============================
// K0: count (g_cnt zero at entry: zero-init on first run, rezero_kernel after)
__global__ void count_kernel(const int* __restrict__ row,
                             const int* __restrict__ et, int E) {
    int e = blockIdx.x * blockDim.x + threadIdx.x;
    if (e >= E) return;
    int t = et[e];
    if (t == NET - 1) return;
    atomicAdd(&g_cnt[row[e] * NET + t], 1u);
}

// K1: single-pass decoupled-lookback exclusive scan: g_cnt -> g_off, g_cur
__global__ void __launch_bounds__(SCAN_BLK) scan_kernel(int nseg) {
    __shared__ unsigned wsum[32];
    __shared__ unsigned s_bid, s_total, s_prefix;
    int tid = threadIdx.x;
    if (tid == 0) s_bid = atomicAdd(&g_ticket, 1u);
    __syncthreads();
    unsigned bid = s_bid;
    int i = bid * SCAN_BLK + tid;
    unsigned v = (i < nseg) ? g_cnt[i] : 0u;
    unsigned incl = block_incl_scan(v, wsum);
    if (tid == SCAN_BLK - 1) s_total = incl;
    __syncthreads();
    if (tid == 0) {
        unsigned total = s_total;
        if (bid == 0) {
            atomicExch(&g_state[0], (2ULL << 32) | (unsigned long long)total);
            s_prefix = 0u;
        } else {
            atomicExch(&g_state[bid], (1ULL << 32) | (unsigned long long)total);
            unsigned running = 0u;
            int idx = (int)bid - 1;
            while (true) {
                unsigned long long s;
                do { s = atomicAdd(&g_state[idx], 0ULL); } while ((unsigned)(s >> 32) == 0u);
                running += (unsigned)s;
                if ((unsigned)(s >> 32) == 2u) break;
                --idx;
            }
            s_prefix = running;
            atomicExch(&g_state[bid], (2ULL << 32) | (unsigned long long)(running + total));
        }
    }
    __syncthreads();
    unsigned off = s_prefix + incl - v;
    if (i < nseg) {
        g_off[i] = off;
        g_cur[i] = off;
        if (i == nseg - 1) g_off[nseg] = off + v;
    }
}

// K2: fill CSR edge list
__global__ void fill_kernel(const int* __restrict__ row,
                            const int* __restrict__ col,
                            const int* __restrict__ et, int E) {
    int e = blockIdx.x * blockDim.x + threadIdx.x;
    if (e >= E) return;
    int t = et[e];
    if (t == NET - 1) return;
    int seg = row[e] * NET + t;
    unsigned pos = atomicAdd(&g_cur[seg], 1u);
    g_elist[pos] = col[e];
}

// ===================== fused aggregate + GEMM + stats ========
// CTA: 128 rows, 512 threads (16 warps, 4x4 warp grid of 32x32 output tiles).
// fp16 m16n8k16 path (same 10 explicit mantissa bits as tf32).
// smem: As [128][68] uint(=half2 kpair), Bs [128][68] uint, sstat[256].
constexpr int APITCH = 68;      // 4B units/row; 68 % 32 == 4 -> conflict-free frag loads
constexpr int SMEM_UINTS = 2 * 128 * APITCH;
constexpr size_t FUSED_SMEM = (size_t)SMEM_UINTS * 4 + 2 * C * 4;   // 70656 B

__global__ void __launch_bounds__(512, 2)
fused_kernel(const float* __restrict__ x, const float* __restrict__ w,
             float* __restrict__ out, int nrows) {
    extern __shared__ uint32_t smu[];
    uint32_t* As = smu;
    uint32_t* Bs = smu + 128 * APITCH;
    float* sstat = reinterpret_cast<float*>(smu + SMEM_UINTS);

    const int tid = threadIdx.x;
    const int wid = tid >> 5, lane = tid & 31;
    const int m0 = blockIdx.x * 128;
    const float4* x4 = reinterpret_cast<const float4*>(x);
    const float4* w4 = reinterpret_cast<const float4*>(w);

    if (tid < 2 * C) sstat[tid] = 0.f;

    const int wm = (wid >> 2) * 32, wn = (wid & 3) * 32;
    const int gr = lane >> 2, gc = lane & 3;

    float acc[2][4][4];
#pragma unroll
    for (int f = 0; f < 2; ++f)
#pragma unroll
        for (int g = 0; g < 4; ++g)
#pragma unroll
            for (int q = 0; q < 4; ++q) acc[f][g][q] = 0.f;

    for (int t = 0; t < NET; ++t) {
        // ---- B_t: W rows [t*128, t*128+128) -> Bs[n][kpair] (transposed, fp16) ----
#pragma unroll
        for (int ch = 0; ch < 4; ++ch) {
            int q = wid + ch * 16;            // k-pair 0..63
            int n4 = lane;                    // float4 col group 0..31
            float4 e0 = w4[(size_t)(t * C + 2 * q) * 32 + n4];       // coalesced
            float4 e1 = w4[(size_t)(t * C + 2 * q + 1) * 32 + n4];
            Bs[(n4 * 4 + 0) * APITCH + q] = pack_h2(e0.x, e1.x);
            Bs[(n4 * 4 + 1) * APITCH + q] = pack_h2(e0.y, e1.y);
            Bs[(n4 * 4 + 2) * APITCH + q] = pack_h2(e0.z, e1.z);
            Bs[(n4 * 4 + 3) * APITCH + q] = pack_h2(e0.w, e1.w);
        }
        // ---- A_t: gather-mean (warp-per-row, 8 rows/warp), fp16 pack ----
        if (t == NET - 1) {
#pragma unroll
            for (int i = 0; i < 8; ++i) {
                int r = wid * 8 + i, gn = m0 + r;
                float4 val = make_float4(0.f, 0.f, 0.f, 0.f);
                if (gn < nrows) val = x4[(size_t)gn * 32 + lane];
                As[r * APITCH + 2 * lane]     = pack_h2(val.x, val.y);
                As[r * APITCH + 2 * lane + 1] = pack_h2(val.z, val.w);
            }
        } else {
            unsigned beg[8], end[8];
#pragma unroll
            for (int i = 0; i < 8; ++i) {
                int gn = m0 + wid * 8 + i;
                if (gn < nrows) {
                    int seg = gn * NET + t;
                    beg[i] = g_off[seg];
                    end[i] = g_off[seg + 1];
                } else { beg[i] = end[i] = 0u; }
            }
#pragma unroll
            for (int i = 0; i < 8; ++i) {
                int r = wid * 8 + i;
                float4 val = make_float4(0.f, 0.f, 0.f, 0.f);
                if (end[i] > beg[i]) {
                    for (unsigned e = beg[i]; e < end[i]; ++e) {
                        int c = g_elist[e];
                        float4 v = x4[(size_t)c * 32 + lane];
                        val.x += v.x; val.y += v.y; val.z += v.z; val.w += v.w;
                    }
                    float inv = 1.0f / (float)(end[i] - beg[i]);
                    val.x *= inv; val.y *= inv; val.z *= inv; val.w *= inv;
                }
                As[r * APITCH + 2 * lane]     = pack_h2(val.x, val.y);
                As[r * APITCH + 2 * lane + 1] = pack_h2(val.z, val.w);
            }
        }
        __syncthreads();
        // ---- MMA: 8 k16-steps over K=128 ----
#pragma unroll
        for (int ks = 0; ks < 8; ++ks) {
            uint32_t a[2][4];
#pragma unroll
            for (int f = 0; f < 2; ++f) {
                const uint32_t* ap = &As[(wm + 16 * f + gr) * APITCH + ks * 8 + gc];
                a[f][0] = ap[0];
                a[f][1] = ap[8 * APITCH];
                a[f][2] = ap[4];
                a[f][3] = ap[8 * APITCH + 4];
            }
#pragma unroll
            for (int g = 0; g < 4; ++g) {
                const uint32_t* bp = &Bs[(wn + 8 * g + gr) * APITCH + ks * 8 + gc];
                uint32_t b0 = bp[0], b1 = bp[4];
#pragma unroll
                for (int f = 0; f < 2; ++f)
                    mma_f16(acc[f][g], a[f], b0, b1);
            }
        }
        __syncthreads();   // before next t overwrites As/Bs
    }

    // ---- epilogue: write out once + fused BN stats ----
#pragma unroll
    for (int f = 0; f < 2; ++f) {
        int r0 = m0 + wm + 16 * f + gr;
#pragma unroll
        for (int g = 0; g < 4; ++g) {
            int cn = wn + 8 * g + gc * 2;
            float s0 = 0.f, q0 = 0.f, s1 = 0.f, q1 = 0.f;
            if (r0 < nrows) {
                float v0 = acc[f][g][0], v1 = acc[f][g][1];
                *reinterpret_cast<float2*>(&out[(size_t)r0 * C + cn]) = make_float2(v0, v1);
                s0 += v0; q0 += v0 * v0; s1 += v1; q1 += v1 * v1;
            }
            if (r0 + 8 < nrows) {
                float v0 = acc[f][g][2], v1 = acc[f][g][3];
                *reinterpret_cast<float2*>(&out[(size_t)(r0 + 8) * C + cn]) = make_float2(v0, v1);
                s0 += v0; q0 += v0 * v0; s1 += v1; q1 += v1 * v1;
            }
            atomicAdd(&sstat[cn], s0);
            atomicAdd(&sstat[C + cn], q0);
            atomicAdd(&sstat[cn + 1], s1);
            atomicAdd(&sstat[C + cn + 1], q1);
        }
    }
    __syncthreads();
    if (tid < 2 * C) atomicAdd(&g_stats[tid], sstat[tid]);
}

// ===================== BN finalize + normalize ===============
__global__ void bnfin_kernel(const float* __restrict__ gamma, const float* __restrict__ beta,
                             float inv_n) {
    int c = threadIdx.x;
    float mean = g_stats[c] * inv_n;
    float var  = g_stats[C + c] * inv_n - mean * mean;
    float sc   = gamma[c] * rsqrtf(var + 1e-5f);
    g_scale[c] = sc;
    g_shift[c] = beta[c] - mean * sc;
}

__global__ void norm_kernel(float* __restrict__ out, size_t n4) {
    size_t i = (size_t)blockIdx.x * blockDim.x + threadIdx.x;
    size_t stride = (size_t)gridDim.x * blockDim.x;
    const float4* sc4 = reinterpret_cast<const float4*>(g_scale);
    const float4* sh4 = reinterpret_cast<const float4*>(g_shift);
    float4* o4 = reinterpret_cast<float4*>(out);
    for (size_t j = i; j < n4; j += stride) {
        int c4 = (int)(j & 31);
        float4 v = o4[j];
        float4 a = sc4[c4], b = sh4[c4];
        v.x = v.x * a.x + b.x;
        v.y = v.y * a.y + b.y;
        v.z = v.z * a.z + b.z;
        v.w = v.w * a.w + b.w;
        o4[j] = v;
    }
}

// tail: restore zero-state for the next replay (first run relies on zero-init)
__global__ void rezero_kernel(int nseg) {
    int i = blockIdx.x * blockDim.x + threadIdx.x;
    int stride = gridDim.x * blockDim.x;
    for (int j = i; j < nseg; j += stride) g_cnt[j] = 0u;
    for (int j = i; j < 1024; j += stride) g_state[j] = 0ULL;
    if (i < 2 * C) g_stats[i] = 0.f;
    if (i == 0) g_ticket = 0u;
}

// ===================== launch ================================
extern "C" void kernel_launch(void* const* d_in, const int* in_sizes, int n_in,
                              void* d_out, int out_size) {
    const float* x     = (const float*)d_in[0];
    const int*   row   = (const int*)d_in[1];   // JAX x64-disabled: int32
    const int*   col   = (const int*)d_in[2];
    const int*   et    = (const int*)d_in[3];
    const float* w     = (const float*)d_in[4];
    const float* gamma = (const float*)d_in[5];
    const float* beta  = (const float*)d_in[6];
    float* out = (float*)d_out;

    int nrows = in_sizes[0] / C;          // 100000
    int E     = in_sizes[1];              // 700000
    int nseg  = nrows * NET;
    int nblk  = (nseg + SCAN_BLK - 1) / SCAN_BLK;

    cudaFuncSetAttribute(fused_kernel, cudaFuncAttributeMaxDynamicSharedMemorySize,
                         (int)FUSED_SMEM);

    count_kernel<<<(E + 255) / 256, 256>>>(row, et, E);                 // 0
    scan_kernel<<<nblk, SCAN_BLK>>>(nseg);                              // 1
    fill_kernel<<<(E + 255) / 256, 256>>>(row, col, et, E);             // 2
    fused_kernel<<<(nrows + 127) / 128, 512, FUSED_SMEM>>>(x, w, out, nrows);  // 3 <- profiled
    bnfin_kernel<<<1, 128>>>(gamma, beta, 1.0f / (float)nrows);         // 4
    norm_kernel<<<2048, 256>>>(out, (size_t)nrows * 32);                // 5
    rezero_kernel<<<512, 256>>>(nseg);                                  // 6
}

// round 9
// speedup vs baseline: 1.7108x; 1.3553x over previous
#include <cuda_runtime.h>
#include <cuda_fp16.h>
#include <cstdint>
#include <cstddef>

// ===================== problem constants =====================
constexpr int C    = 128;            // channels
constexpr int NET  = 7;              // edge types
constexpr int NMAX = 100000;
constexpr int NSEGMAX = NMAX * NET;  // 700000
constexpr int EMAX = 700000;
constexpr int SCAN_BLK = 1024;

// ===================== device scratch ========================
__device__ unsigned g_cnt[NSEGMAX];             // zero-init; re-zeroed by scan
__device__ unsigned g_off[NSEGMAX + 1];         // CSR offsets
__device__ unsigned g_cur[NSEGMAX];             // fill cursors
__device__ int      g_elist[EMAX];              // col index per CSR slot
__device__ unsigned g_ticket;                   // zero-init; re-zeroed by fill
__device__ unsigned long long g_state[1024];    // zero-init; re-zeroed by fill
__device__ float    g_stats[2 * C];             // zero-init; re-zeroed by bnfin
__device__ float    g_scale[C];
__device__ float    g_shift[C];

// ===================== helpers ===============================
__device__ __forceinline__ uint32_t pack_h2(float a, float b) {
    __half2 h = __floats2half2_rn(a, b);
    return *reinterpret_cast<uint32_t*>(&h);
}
__device__ __forceinline__ uint32_t smem_u32(const void* p) {
    uint32_t a;
    asm("{ .reg .u64 t; cvta.to.shared.u64 t, %1; cvt.u32.u64 %0, t; }" : "=r"(a) : "l"(p));
    return a;
}
__device__ __forceinline__ void mma_f16(float* d, const uint32_t* a, uint32_t b0, uint32_t b1) {
    asm volatile(
        "mma.sync.aligned.m16n8k16.row.col.f32.f16.f16.f32 "
        "{%0,%1,%2,%3}, {%4,%5,%6,%7}, {%8,%9}, {%0,%1,%2,%3};"
        : "+f"(d[0]), "+f"(d[1]), "+f"(d[2]), "+f"(d[3])
        : "r"(a[0]), "r"(a[1]), "r"(a[2]), "r"(a[3]), "r"(b0), "r"(b1));
}
#define LDSM_X4(r, addr)                                                        \
    asm volatile("ldmatrix.sync.aligned.m8n8.x4.shared.b16 {%0,%1,%2,%3}, [%4];"\
        : "=r"((r)[0]), "=r"((r)[1]), "=r"((r)[2]), "=r"((r)[3]) : "r"(addr))
#define LDSM_X4_T(r, addr)                                                      \
    asm volatile("ldmatrix.sync.aligned.m8n8.x4.trans.shared.b16 {%0,%1,%2,%3}, [%4];"\
        : "=r"((r)[0]), "=r"((r)[1]), "=r"((r)[2]), "=r"((r)[3]) : "r"(addr))

__device__ unsigned block_incl_scan(unsigned v, unsigned* wsum) {
    int lane = threadIdx.x & 31, wid = threadIdx.x >> 5;
#pragma unroll
    for (int d = 1; d < 32; d <<= 1) {
        unsigned n = __shfl_up_sync(0xffffffff, v, d);
        if (lane >= d) v += n;
    }
    if (lane == 31) wsum[wid] = v;
    __syncthreads();
    if (wid == 0) {
        unsigned w = wsum[lane];
#pragma unroll
        for (int d = 1; d < 32; d <<= 1) {
            unsigned n = __shfl_up_sync(0xffffffff, w, d);
            if (lane >= d) w += n;
        }
        wsum[lane] = w;
    }
    __syncthreads();
    return v + (wid > 0 ? wsum[wid - 1] : 0u);
}

// ===================== CSR build =============================
__global__ void count_kernel(const int* __restrict__ row,
                             const int* __restrict__ et, int E) {
    int e = blockIdx.x * blockDim.x + threadIdx.x;
    if (e >= E) return;
    int t = et[e];
    if (t == NET - 1) return;
    atomicAdd(&g_cnt[row[e] * NET + t], 1u);
}

// single-pass decoupled-lookback exclusive scan; also re-zeroes g_cnt
__global__ void __launch_bounds__(SCAN_BLK) scan_kernel(int nseg) {
    __shared__ unsigned wsum[32];
    __shared__ unsigned s_bid, s_total, s_prefix;
    int tid = threadIdx.x;
    if (tid == 0) s_bid = atomicAdd(&g_ticket, 1u);
    __syncthreads();
    unsigned bid = s_bid;
    int i = bid * SCAN_BLK + tid;
    unsigned v = (i < nseg) ? g_cnt[i] : 0u;
    if (i < nseg) g_cnt[i] = 0u;                 // restore for next replay
    unsigned incl = block_incl_scan(v, wsum);
    if (tid == SCAN_BLK - 1) s_total = incl;
    __syncthreads();
    if (tid == 0) {
        unsigned total = s_total;
        if (bid == 0) {
            atomicExch(&g_state[0], (2ULL << 32) | (unsigned long long)total);
            s_prefix = 0u;
        } else {
            atomicExch(&g_state[bid], (1ULL << 32) | (unsigned long long)total);
            unsigned running = 0u;
            int idx = (int)bid - 1;
            while (true) {
                unsigned long long s;
                do { s = atomicAdd(&g_state[idx], 0ULL); } while ((unsigned)(s >> 32) == 0u);
                running += (unsigned)s;
                if ((unsigned)(s >> 32) == 2u) break;
                --idx;
            }
            s_prefix = running;
            atomicExch(&g_state[bid], (2ULL << 32) | (unsigned long long)(running + total));
        }
    }
    __syncthreads();
    unsigned off = s_prefix + incl - v;
    if (i < nseg) {
        g_off[i] = off;
        g_cur[i] = off;
        if (i == nseg - 1) g_off[nseg] = off + v;
    }
}

// fill CSR edge list; also re-zeroes scan state for next replay
__global__ void fill_kernel(const int* __restrict__ row,
                            const int* __restrict__ col,
                            const int* __restrict__ et, int E) {
    int e = blockIdx.x * blockDim.x + threadIdx.x;
    if (e < 1024) g_state[e] = 0ULL;
    if (e == 0) g_ticket = 0u;
    if (e >= E) return;
    int t = et[e];
    if (t == NET - 1) return;
    int seg = row[e] * NET + t;
    unsigned pos = atomicAdd(&g_cur[seg], 1u);
    g_elist[pos] = col[e];
}

// ===================== fused aggregate + GEMM + stats ========
// CTA: 128 rows, 512 threads (16 warps, 4x4 grid of 32x32 output tiles).
// SMEM (uints): As[128][68], Bs[128][68] (both 272B rows: 16B-aligned for
// ldmatrix, start-bank step 4 -> conflict-free), selist[4096], soff[128*8],
// sstat[256 floats].
constexpr int APITCH = 68;       // uints per A row (136 halfs)
constexpr int BPITCH = 68;       // uints per B k-row (136 halfs)  [was 66: misaligned!]
constexpr int ECAP   = 4096;
constexpr int OFF_AS = 0;
constexpr int OFF_BS = OFF_AS + 128 * APITCH;      // 8704
constexpr int OFF_EL = OFF_BS + 128 * BPITCH;      // 17408
constexpr int OFF_SOFF = OFF_EL + ECAP;            // 21504
constexpr int OFF_STAT = OFF_SOFF + 128 * 8;       // 22528
constexpr int SMEM_UINTS = OFF_STAT + 2 * C;       // 22784
constexpr size_t FUSED_SMEM = (size_t)SMEM_UINTS * 4;   // 91136 B

__global__ void __launch_bounds__(512, 2)
fused_kernel(const float* __restrict__ x, const float* __restrict__ w,
             float* __restrict__ out, int nrows) {
    extern __shared__ uint32_t smu[];
    uint32_t* As = smu + OFF_AS;
    uint32_t* Bs = smu + OFF_BS;
    int*      selist = reinterpret_cast<int*>(smu + OFF_EL);
    unsigned* soff = smu + OFF_SOFF;
    float*    sstat = reinterpret_cast<float*>(smu + OFF_STAT);

    const int tid = threadIdx.x;
    const int wid = tid >> 5, lane = tid & 31;
    const int m0 = blockIdx.x * 128;
    const int rlim = min(128, nrows - m0);
    const float4* x4 = reinterpret_cast<const float4*>(x);
    const float4* w4 = reinterpret_cast<const float4*>(w);

    if (tid < 2 * C) sstat[tid] = 0.f;

    // ---- stage CTA segment offsets: soff[r][j] = g_off[(m0+r)*7 + j] ----
#pragma unroll
    for (int i = 0; i < 2; ++i) {
        int idx = tid + i * 512;                 // 0..1023
        int r = idx >> 3, j = idx & 7;
        soff[idx] = (r < rlim) ? g_off[(m0 + r) * NET + j] : 0u;
    }
    __syncthreads();
    const unsigned e0   = soff[0];               // CTA edge range start
    const unsigned etot = soff[(rlim - 1) * 8 + 7] - e0;
    // ---- stage edge list (coalesced); overflow falls back to global ----
    for (unsigned i = tid; i < min(etot, (unsigned)ECAP); i += 512)
        selist[i] = g_elist[e0 + i];
    __syncthreads();

    const int wm = (wid >> 2) * 32, wn = (wid & 3) * 32;
    const int gr = lane >> 2, gc = lane & 3;
    const int grp = lane >> 3, rr = lane & 7;

    // ldmatrix per-thread smem byte addresses
    const uint32_t sbase = smem_u32(smu);
    const uint32_t abase = sbase + OFF_AS * 4;
    const uint32_t bbase = sbase + OFF_BS * 4;
    // A (non-trans): m0..m3 = {rows wm+(grp&1)*8+rr, k halves (grp>>1)*8}
    uint32_t aadr0 = abase + (wm + (grp & 1) * 8 + rr) * APITCH * 4 + (grp >> 1) * 16;
    uint32_t aadr1 = aadr0 + 16 * APITCH * 4;
    // B (trans): m0..m3 = {k rows (grp&1)*8+rr, n cols wn+(grp>>1)*8}
    uint32_t badr0 = bbase + ((grp & 1) * 8 + rr) * BPITCH * 4 + (wn + (grp >> 1) * 8) * 2;
    uint32_t badr1 = badr0 + 16 * 2;             // +16 n cols

    float acc[2][4][4];
#pragma unroll
    for (int f = 0; f < 2; ++f)
#pragma unroll
        for (int g = 0; g < 4; ++g)
#pragma unroll
            for (int q = 0; q < 4; ++q) acc[f][g][q] = 0.f;

    for (int t = 0; t < NET; ++t) {
        // ---- B_t: W[t*128+k][n] -> Bs[k][n] fp16, natural K x N layout ----
#pragma unroll
        for (int i = 0; i < 8; ++i) {
            int e = tid + i * 512;               // 0..4095
            int k = e >> 5, n4 = e & 31;
            float4 v = w4[(size_t)(t * C + k) * 32 + n4];
            *reinterpret_cast<uint2*>(&Bs[k * BPITCH + n4 * 2]) =
                make_uint2(pack_h2(v.x, v.y), pack_h2(v.z, v.w));
        }
        // ---- A_t: gather-mean, warp-per-row (8 rows/warp) ----
#pragma unroll
        for (int i = 0; i < 8; ++i) {
            int r = wid * 8 + i;
            float4 val = make_float4(0.f, 0.f, 0.f, 0.f);
            if (r < rlim) {
                if (t == NET - 1) {
                    val = x4[(size_t)(m0 + r) * 32 + lane];      // self slot
                } else {
                    unsigned beg = soff[r * 8 + t] - e0;
                    unsigned end = soff[r * 8 + t + 1] - e0;
                    for (unsigned e = beg; e < end; ++e) {
                        int c = (e < (unsigned)ECAP) ? selist[e] : g_elist[e0 + e];
                        float4 v = x4[(size_t)c * 32 + lane];
                        val.x += v.x; val.y += v.y; val.z += v.z; val.w += v.w;
                    }
                    if (end > beg) {
                        float inv = 1.0f / (float)(end - beg);
                        val.x *= inv; val.y *= inv; val.z *= inv; val.w *= inv;
                    }
                }
            }
            *reinterpret_cast<uint2*>(&As[r * APITCH + 2 * lane]) =
                make_uint2(pack_h2(val.x, val.y), pack_h2(val.z, val.w));
        }
        __syncthreads();
        // ---- MMA: 8 k16-steps, ldmatrix operands ----
#pragma unroll
        for (int ks = 0; ks < 8; ++ks) {
            uint32_t af0[4], af1[4], bf0[4], bf1[4];
            LDSM_X4(af0, aadr0 + ks * 32);                     // +16 halfs per ks
            LDSM_X4(af1, aadr1 + ks * 32);
            LDSM_X4_T(bf0, badr0 + ks * 16 * BPITCH * 4);      // +16 k-rows per ks
            LDSM_X4_T(bf1, badr1 + ks * 16 * BPITCH * 4);
            mma_f16(acc[0][0], af0, bf0[0], bf0[1]);
            mma_f16(acc[0][1], af0, bf0[2], bf0[3]);
            mma_f16(acc[0][2], af0, bf1[0], bf1[1]);
            mma_f16(acc[0][3], af0, bf1[2], bf1[3]);
            mma_f16(acc[1][0], af1, bf0[0], bf0[1]);
            mma_f16(acc[1][1], af1, bf0[2], bf0[3]);
            mma_f16(acc[1][2], af1, bf1[0], bf1[1]);
            mma_f16(acc[1][3], af1, bf1[2], bf1[3]);
        }
        __syncthreads();   // before next t overwrites As/Bs
    }

    // ---- epilogue: write out once + fused BN stats ----
#pragma unroll
    for (int f = 0; f < 2; ++f) {
        int r0 = m0 + wm + 16 * f + gr;
#pragma unroll
        for (int g = 0; g < 4; ++g) {
            int cn = wn + 8 * g + gc * 2;
            float s0 = 0.f, q0 = 0.f, s1 = 0.f, q1 = 0.f;
            if (r0 < nrows) {
                float v0 = acc[f][g][0], v1 = acc[f][g][1];
                *reinterpret_cast<float2*>(&out[(size_t)r0 * C + cn]) = make_float2(v0, v1);
                s0 += v0; q0 += v0 * v0; s1 += v1; q1 += v1 * v1;
            }
            if (r0 + 8 < nrows) {
                float v0 = acc[f][g][2], v1 = acc[f][g][3];
                *reinterpret_cast<float2*>(&out[(size_t)(r0 + 8) * C + cn]) = make_float2(v0, v1);
                s0 += v0; q0 += v0 * v0; s1 += v1; q1 += v1 * v1;
            }
            atomicAdd(&sstat[cn], s0);
            atomicAdd(&sstat[C + cn], q0);
            atomicAdd(&sstat[cn + 1], s1);
            atomicAdd(&sstat[C + cn + 1], q1);
        }
    }
    __syncthreads();
    if (tid < 2 * C) atomicAdd(&g_stats[tid], sstat[tid]);
}

// ===================== BN finalize + normalize ===============
__global__ void bnfin_kernel(const float* __restrict__ gamma, const float* __restrict__ beta,
                             float inv_n) {
    int c = threadIdx.x;
    float mean = g_stats[c] * inv_n;
    float var  = g_stats[C + c] * inv_n - mean * mean;
    float sc   = gamma[c] * rsqrtf(var + 1e-5f);
    g_scale[c] = sc;
    g_shift[c] = beta[c] - mean * sc;
    g_stats[c] = 0.f;                 // restore for next replay
    g_stats[C + c] = 0.f;
}

__global__ void norm_kernel(float* __restrict__ out, size_t n4) {
    size_t i = (size_t)blockIdx.x * blockDim.x + threadIdx.x;
    size_t stride = (size_t)gridDim.x * blockDim.x;
    const float4* sc4 = reinterpret_cast<const float4*>(g_scale);
    const float4* sh4 = reinterpret_cast<const float4*>(g_shift);
    float4* o4 = reinterpret_cast<float4*>(out);
    for (size_t j = i; j < n4; j += stride) {
        int c4 = (int)(j & 31);
        float4 v = o4[j];
        float4 a = sc4[c4], b = sh4[c4];
        v.x = v.x * a.x + b.x;
        v.y = v.y * a.y + b.y;
        v.z = v.z * a.z + b.z;
        v.w = v.w * a.w + b.w;
        o4[j] = v;
    }
}

// ===================== launch ================================
extern "C" void kernel_launch(void* const* d_in, const int* in_sizes, int n_in,
                              void* d_out, int out_size) {
    const float* x     = (const float*)d_in[0];
    const int*   row   = (const int*)d_in[1];   // JAX x64-disabled: int32
    const int*   col   = (const int*)d_in[2];
    const int*   et    = (const int*)d_in[3];
    const float* w     = (const float*)d_in[4];
    const float* gamma = (const float*)d_in[5];
    const float* beta  = (const float*)d_in[6];
    float* out = (float*)d_out;

    int nrows = in_sizes[0] / C;          // 100000
    int E     = in_sizes[1];              // 700000
    int nseg  = nrows * NET;
    int nblk  = (nseg + SCAN_BLK - 1) / SCAN_BLK;

    cudaFuncSetAttribute(fused_kernel, cudaFuncAttributeMaxDynamicSharedMemorySize,
                         (int)FUSED_SMEM);

    count_kernel<<<(E + 255) / 256, 256>>>(row, et, E);                         // 0
    scan_kernel<<<nblk, SCAN_BLK>>>(nseg);                                      // 1
    fill_kernel<<<(E + 255) / 256, 256>>>(row, col, et, E);                     // 2
    fused_kernel<<<(nrows + 127) / 128, 512, FUSED_SMEM>>>(x, w, out, nrows);   // 3 <- profiled
    bnfin_kernel<<<1, 128>>>(gamma, beta, 1.0f / (float)nrows);                 // 4
    norm_kernel<<<2048, 256>>>(out, (size_t)nrows * 32);                        // 5
}

// round 10
// speedup vs baseline: 1.7331x; 1.0130x over previous
#include <cuda_runtime.h>
#include <cuda_fp16.h>
#include <cstdint>
#include <cstddef>

// ===================== problem constants =====================
constexpr int C    = 128;            // channels
constexpr int NET  = 7;              // edge types
constexpr int NMAX = 100000;
constexpr int NSEGMAX = NMAX * NET;  // 700000
constexpr int EMAX = 700000;
constexpr int SCAN_BLK = 1024;

// ===================== device scratch ========================
__device__ unsigned g_cnt[NSEGMAX];             // zero-init; re-zeroed by scan
__device__ unsigned g_off[NSEGMAX + 1];         // CSR offsets
__device__ unsigned g_cur[NSEGMAX];             // fill cursors
__device__ int      g_elist[EMAX];              // col index per CSR slot
__device__ unsigned g_ticket;                   // zero-init; re-zeroed by fill
__device__ unsigned long long g_state[1024];    // zero-init; re-zeroed by fill
__device__ float    g_stats[2 * C];             // zero-init; re-zeroed by bnfin
__device__ float    g_scale[C];
__device__ float    g_shift[C];

// ===================== helpers ===============================
__device__ __forceinline__ uint32_t pack_h2(float a, float b) {
    __half2 h = __floats2half2_rn(a, b);
    return *reinterpret_cast<uint32_t*>(&h);
}
__device__ __forceinline__ uint32_t smem_u32(const void* p) {
    uint32_t a;
    asm("{ .reg .u64 t; cvta.to.shared.u64 t, %1; cvt.u32.u64 %0, t; }" : "=r"(a) : "l"(p));
    return a;
}
__device__ __forceinline__ void mma_f16(float* d, const uint32_t* a, uint32_t b0, uint32_t b1) {
    asm volatile(
        "mma.sync.aligned.m16n8k16.row.col.f32.f16.f16.f32 "
        "{%0,%1,%2,%3}, {%4,%5,%6,%7}, {%8,%9}, {%0,%1,%2,%3};"
        : "+f"(d[0]), "+f"(d[1]), "+f"(d[2]), "+f"(d[3])
        : "r"(a[0]), "r"(a[1]), "r"(a[2]), "r"(a[3]), "r"(b0), "r"(b1));
}
#define LDSM_X4(r, addr)                                                        \
    asm volatile("ldmatrix.sync.aligned.m8n8.x4.shared.b16 {%0,%1,%2,%3}, [%4];"\
        : "=r"((r)[0]), "=r"((r)[1]), "=r"((r)[2]), "=r"((r)[3]) : "r"(addr))
#define LDSM_X4_T(r, addr)                                                      \
    asm volatile("ldmatrix.sync.aligned.m8n8.x4.trans.shared.b16 {%0,%1,%2,%3}, [%4];"\
        : "=r"((r)[0]), "=r"((r)[1]), "=r"((r)[2]), "=r"((r)[3]) : "r"(addr))

__device__ unsigned block_incl_scan(unsigned v, unsigned* wsum) {
    int lane = threadIdx.x & 31, wid = threadIdx.x >> 5;
#pragma unroll
    for (int d = 1; d < 32; d <<= 1) {
        unsigned n = __shfl_up_sync(0xffffffff, v, d);
        if (lane >= d) v += n;
    }
    if (lane == 31) wsum[wid] = v;
    __syncthreads();
    if (wid == 0) {
        unsigned w = wsum[lane];
#pragma unroll
        for (int d = 1; d < 32; d <<= 1) {
            unsigned n = __shfl_up_sync(0xffffffff, w, d);
            if (lane >= d) w += n;
        }
        wsum[lane] = w;
    }
    __syncthreads();
    return v + (wid > 0 ? wsum[wid - 1] : 0u);
}

// ===================== CSR build =============================
__global__ void count_kernel(const int* __restrict__ row,
                             const int* __restrict__ et, int E) {
    int e = blockIdx.x * blockDim.x + threadIdx.x;
    if (e >= E) return;
    int t = et[e];
    if (t == NET - 1) return;
    atomicAdd(&g_cnt[row[e] * NET + t], 1u);
}

// single-pass decoupled-lookback exclusive scan; also re-zeroes g_cnt
__global__ void __launch_bounds__(SCAN_BLK) scan_kernel(int nseg) {
    __shared__ unsigned wsum[32];
    __shared__ unsigned s_bid, s_total, s_prefix;
    int tid = threadIdx.x;
    if (tid == 0) s_bid = atomicAdd(&g_ticket, 1u);
    __syncthreads();
    unsigned bid = s_bid;
    int i = bid * SCAN_BLK + tid;
    unsigned v = (i < nseg) ? g_cnt[i] : 0u;
    if (i < nseg) g_cnt[i] = 0u;                 // restore for next replay
    unsigned incl = block_incl_scan(v, wsum);
    if (tid == SCAN_BLK - 1) s_total = incl;
    __syncthreads();
    if (tid == 0) {
        unsigned total = s_total;
        if (bid == 0) {
            atomicExch(&g_state[0], (2ULL << 32) | (unsigned long long)total);
            s_prefix = 0u;
        } else {
            atomicExch(&g_state[bid], (1ULL << 32) | (unsigned long long)total);
            unsigned running = 0u;
            int idx = (int)bid - 1;
            while (true) {
                unsigned long long s;
                do { s = atomicAdd(&g_state[idx], 0ULL); } while ((unsigned)(s >> 32) == 0u);
                running += (unsigned)s;
                if ((unsigned)(s >> 32) == 2u) break;
                --idx;
            }
            s_prefix = running;
            atomicExch(&g_state[bid], (2ULL << 32) | (unsigned long long)(running + total));
        }
    }
    __syncthreads();
    unsigned off = s_prefix + incl - v;
    if (i < nseg) {
        g_off[i] = off;
        g_cur[i] = off;
        if (i == nseg - 1) g_off[nseg] = off + v;
    }
}

// fill CSR edge list; also re-zeroes scan state for next replay
__global__ void fill_kernel(const int* __restrict__ row,
                            const int* __restrict__ col,
                            const int* __restrict__ et, int E) {
    int e = blockIdx.x * blockDim.x + threadIdx.x;
    if (e < 1024) g_state[e] = 0ULL;
    if (e == 0) g_ticket = 0u;
    if (e >= E) return;
    int t = et[e];
    if (t == NET - 1) return;
    int seg = row[e] * NET + t;
    unsigned pos = atomicAdd(&g_cur[seg], 1u);
    g_elist[pos] = col[e];
}

// ===================== fused aggregate + GEMM + stats ========
// CTA: 128 rows, 512 threads (16 warps, 4x4 grid of 32x32 output tiles).
// SMEM (uints): As[128][68], Bs[128][68] (both 272B rows: 16B-aligned for
// ldmatrix, start-bank step 4 -> conflict-free), selist[4096], soff[128*8],
// sstat[256 floats].
constexpr int APITCH = 68;       // uints per A row (136 halfs)
constexpr int BPITCH = 68;       // uints per B k-row (136 halfs)  [was 66: misaligned!]
constexpr int ECAP   = 4096;
constexpr int OFF_AS = 0;
constexpr int OFF_BS = OFF_AS + 128 * APITCH;      // 8704
constexpr int OFF_EL = OFF_BS + 128 * BPITCH;      // 17408
constexpr int OFF_SOFF = OFF_EL + ECAP;            // 21504
constexpr int OFF_STAT = OFF_SOFF + 128 * 8;       // 22528
constexpr int SMEM_UINTS = OFF_STAT + 2 * C;       // 22784
constexpr size_t FUSED_SMEM = (size_t)SMEM_UINTS * 4;   // 91136 B

__global__ void __launch_bounds__(512, 2)
fused_kernel(const float* __restrict__ x, const float* __restrict__ w,
             float* __restrict__ out, int nrows) {
    extern __shared__ uint32_t smu[];
    uint32_t* As = smu + OFF_AS;
    uint32_t* Bs = smu + OFF_BS;
    int*      selist = reinterpret_cast<int*>(smu + OFF_EL);
    unsigned* soff = smu + OFF_SOFF;
    float*    sstat = reinterpret_cast<float*>(smu + OFF_STAT);

    const int tid = threadIdx.x;
    const int wid = tid >> 5, lane = tid & 31;
    const int m0 = blockIdx.x * 128;
    const int rlim = min(128, nrows - m0);
    const float4* x4 = reinterpret_cast<const float4*>(x);
    const float4* w4 = reinterpret_cast<const float4*>(w);

    if (tid < 2 * C) sstat[tid] = 0.f;

    // ---- stage CTA segment offsets: soff[r][j] = g_off[(m0+r)*7 + j] ----
#pragma unroll
    for (int i = 0; i < 2; ++i) {
        int idx = tid + i * 512;                 // 0..1023
        int r = idx >> 3, j = idx & 7;
        soff[idx] = (r < rlim) ? g_off[(m0 + r) * NET + j] : 0u;
    }
    __syncthreads();
    const unsigned e0   = soff[0];               // CTA edge range start
    const unsigned etot = soff[(rlim - 1) * 8 + 7] - e0;
    // ---- stage edge list (coalesced); overflow falls back to global ----
    for (unsigned i = tid; i < min(etot, (unsigned)ECAP); i += 512)
        selist[i] = g_elist[e0 + i];
    __syncthreads();

    const int wm = (wid >> 2) * 32, wn = (wid & 3) * 32;
    const int gr = lane >> 2, gc = lane & 3;
    const int grp = lane >> 3, rr = lane & 7;

    // ldmatrix per-thread smem byte addresses
    const uint32_t sbase = smem_u32(smu);
    const uint32_t abase = sbase + OFF_AS * 4;
    const uint32_t bbase = sbase + OFF_BS * 4;
    // A (non-trans): m0..m3 = {rows wm+(grp&1)*8+rr, k halves (grp>>1)*8}
    uint32_t aadr0 = abase + (wm + (grp & 1) * 8 + rr) * APITCH * 4 + (grp >> 1) * 16;
    uint32_t aadr1 = aadr0 + 16 * APITCH * 4;
    // B (trans): m0..m3 = {k rows (grp&1)*8+rr, n cols wn+(grp>>1)*8}
    uint32_t badr0 = bbase + ((grp & 1) * 8 + rr) * BPITCH * 4 + (wn + (grp >> 1) * 8) * 2;
    uint32_t badr1 = badr0 + 16 * 2;             // +16 n cols

    float acc[2][4][4];
#pragma unroll
    for (int f = 0; f < 2; ++f)
#pragma unroll
        for (int g = 0; g < 4; ++g)
#pragma unroll
            for (int q = 0; q < 4; ++q) acc[f][g][q] = 0.f;

    for (int t = 0; t < NET; ++t) {
        // ---- B_t: W[t*128+k][n] -> Bs[k][n] fp16, natural K x N layout ----
#pragma unroll
        for (int i = 0; i < 8; ++i) {
            int e = tid + i * 512;               // 0..4095
            int k = e >> 5, n4 = e & 31;
            float4 v = w4[(size_t)(t * C + k) * 32 + n4];
            *reinterpret_cast<uint2*>(&Bs[k * BPITCH + n4 * 2]) =
                make_uint2(pack_h2(v.x, v.y), pack_h2(v.z, v.w));
        }
        // ---- A_t: gather-mean, warp-per-row (8 rows/warp) ----
#pragma unroll
        for (int i = 0; i < 8; ++i) {
            int r = wid * 8 + i;
            float4 val = make_float4(0.f, 0.f, 0.f, 0.f);
            if (r < rlim) {
                if (t == NET - 1) {
                    val = x4[(size_t)(m0 + r) * 32 + lane];      // self slot
                } else {
                    unsigned beg = soff[r * 8 + t] - e0;
                    unsigned end = soff[r * 8 + t + 1] - e0;
                    for (unsigned e = beg; e < end; ++e) {
                        int c = (e < (unsigned)ECAP) ? selist[e] : g_elist[e0 + e];
                        float4 v = x4[(size_t)c * 32 + lane];
                        val.x += v.x; val.y += v.y; val.z += v.z; val.w += v.w;
                    }
                    if (end > beg) {
                        float inv = 1.0f / (float)(end - beg);
                        val.x *= inv; val.y *= inv; val.z *= inv; val.w *= inv;
                    }
                }
            }
            *reinterpret_cast<uint2*>(&As[r * APITCH + 2 * lane]) =
                make_uint2(pack_h2(val.x, val.y), pack_h2(val.z, val.w));
        }
        __syncthreads();
        // ---- MMA: 8 k16-steps, ldmatrix operands ----
#pragma unroll
        for (int ks = 0; ks < 8; ++ks) {
            uint32_t af0[4], af1[4], bf0[4], bf1[4];
            LDSM_X4(af0, aadr0 + ks * 32);                     // +16 halfs per ks
            LDSM_X4(af1, aadr1 + ks * 32);
            LDSM_X4_T(bf0, badr0 + ks * 16 * BPITCH * 4);      // +16 k-rows per ks
            LDSM_X4_T(bf1, badr1 + ks * 16 * BPITCH * 4);
            mma_f16(acc[0][0], af0, bf0[0], bf0[1]);
            mma_f16(acc[0][1], af0, bf0[2], bf0[3]);
            mma_f16(acc[0][2], af0, bf1[0], bf1[1]);
            mma_f16(acc[0][3], af0, bf1[2], bf1[3]);
            mma_f16(acc[1][0], af1, bf0[0], bf0[1]);
            mma_f16(acc[1][1], af1, bf0[2], bf0[3]);
            mma_f16(acc[1][2], af1, bf1[0], bf1[1]);
            mma_f16(acc[1][3], af1, bf1[2], bf1[3]);
        }
        __syncthreads();   // before next t overwrites As/Bs
    }

    // ---- epilogue: write out once + fused BN stats ----
#pragma unroll
    for (int f = 0; f < 2; ++f) {
        int r0 = m0 + wm + 16 * f + gr;
#pragma unroll
        for (int g = 0; g < 4; ++g) {
            int cn = wn + 8 * g + gc * 2;
            float s0 = 0.f, q0 = 0.f, s1 = 0.f, q1 = 0.f;
            if (r0 < nrows) {
                float v0 = acc[f][g][0], v1 = acc[f][g][1];
                *reinterpret_cast<float2*>(&out[(size_t)r0 * C + cn]) = make_float2(v0, v1);
                s0 += v0; q0 += v0 * v0; s1 += v1; q1 += v1 * v1;
            }
            if (r0 + 8 < nrows) {
                float v0 = acc[f][g][2], v1 = acc[f][g][3];
                *reinterpret_cast<float2*>(&out[(size_t)(r0 + 8) * C + cn]) = make_float2(v0, v1);
                s0 += v0; q0 += v0 * v0; s1 += v1; q1 += v1 * v1;
            }
            atomicAdd(&sstat[cn], s0);
            atomicAdd(&sstat[C + cn], q0);
            atomicAdd(&sstat[cn + 1], s1);
            atomicAdd(&sstat[C + cn + 1], q1);
        }
    }
    __syncthreads();
    if (tid < 2 * C) atomicAdd(&g_stats[tid], sstat[tid]);
}

// ===================== BN finalize + normalize ===============
__global__ void bnfin_kernel(const float* __restrict__ gamma, const float* __restrict__ beta,
                             float inv_n) {
    int c = threadIdx.x;
    float mean = g_stats[c] * inv_n;
    float var  = g_stats[C + c] * inv_n - mean * mean;
    float sc   = gamma[c] * rsqrtf(var + 1e-5f);
    g_scale[c] = sc;
    g_shift[c] = beta[c] - mean * sc;
    g_stats[c] = 0.f;                 // restore for next replay
    g_stats[C + c] = 0.f;
}

__global__ void norm_kernel(float* __restrict__ out, size_t n4) {
    size_t i = (size_t)blockIdx.x * blockDim.x + threadIdx.x;
    size_t stride = (size_t)gridDim.x * blockDim.x;
    const float4* sc4 = reinterpret_cast<const float4*>(g_scale);
    const float4* sh4 = reinterpret_cast<const float4*>(g_shift);
    float4* o4 = reinterpret_cast<float4*>(out);
    for (size_t j = i; j < n4; j += stride) {
        int c4 = (int)(j & 31);
        float4 v = o4[j];
        float4 a = sc4[c4], b = sh4[c4];
        v.x = v.x * a.x + b.x;
        v.y = v.y * a.y + b.y;
        v.z = v.z * a.z + b.z;
        v.w = v.w * a.w + b.w;
        o4[j] = v;
    }
}

// ===================== launch ================================
extern "C" void kernel_launch(void* const* d_in, const int* in_sizes, int n_in,
                              void* d_out, int out_size) {
    const float* x     = (const float*)d_in[0];
    const int*   row   = (const int*)d_in[1];   // JAX x64-disabled: int32
    const int*   col   = (const int*)d_in[2];
    const int*   et    = (const int*)d_in[3];
    const float* w     = (const float*)d_in[4];
    const float* gamma = (const float*)d_in[5];
    const float* beta  = (const float*)d_in[6];
    float* out = (float*)d_out;

    int nrows = in_sizes[0] / C;          // 100000
    int E     = in_sizes[1];              // 700000
    int nseg  = nrows * NET;
    int nblk  = (nseg + SCAN_BLK - 1) / SCAN_BLK;

    cudaFuncSetAttribute(fused_kernel, cudaFuncAttributeMaxDynamicSharedMemorySize,
                         (int)FUSED_SMEM);

    count_kernel<<<(E + 255) / 256, 256>>>(row, et, E);                         // 0
    scan_kernel<<<nblk, SCAN_BLK>>>(nseg);                                      // 1
    fill_kernel<<<(E + 255) / 256, 256>>>(row, col, et, E);                     // 2
    fused_kernel<<<(nrows + 127) / 128, 512, FUSED_SMEM>>>(x, w, out, nrows);   // 3 <- profiled
    bnfin_kernel<<<1, 128>>>(gamma, beta, 1.0f / (float)nrows);                 // 4
    norm_kernel<<<2048, 256>>>(out, (size_t)nrows * 32);                        // 5
}

// round 11
// speedup vs baseline: 1.7333x; 1.0001x over previous
#include <cuda_runtime.h>
#include <cuda_fp16.h>
#include <cstdint>
#include <cstddef>

// ===================== problem constants =====================
constexpr int C    = 128;            // channels
constexpr int NET  = 7;              // edge types
constexpr int NMAX = 100000;
constexpr int NSEGMAX = NMAX * NET;  // 700000
constexpr int EMAX = 700000;
constexpr int SCAN_BLK = 1024;

// ===================== device scratch ========================
__device__ unsigned g_cnt[NSEGMAX];             // zero-init; re-zeroed by scan
__device__ unsigned g_off[NSEGMAX + 1];         // CSR offsets
__device__ unsigned g_cur[NSEGMAX];             // fill cursors
__device__ int      g_elist[EMAX];              // col index per CSR slot
__device__ unsigned g_ticket;                   // zero-init; re-zeroed by fill
__device__ unsigned long long g_state[1024];    // zero-init; re-zeroed by fill
__device__ float    g_stats[2 * C];             // zero-init; re-zeroed by bnfin
__device__ float    g_scale[C];
__device__ float    g_shift[C];

// ===================== helpers ===============================
__device__ __forceinline__ uint32_t pack_h2(float a, float b) {
    __half2 h = __floats2half2_rn(a, b);
    return *reinterpret_cast<uint32_t*>(&h);
}
__device__ __forceinline__ uint32_t smem_u32(const void* p) {
    uint32_t a;
    asm("{ .reg .u64 t; cvta.to.shared.u64 t, %1; cvt.u32.u64 %0, t; }" : "=r"(a) : "l"(p));
    return a;
}
__device__ __forceinline__ void mma_f16(float* d, const uint32_t* a, uint32_t b0, uint32_t b1) {
    asm volatile(
        "mma.sync.aligned.m16n8k16.row.col.f32.f16.f16.f32 "
        "{%0,%1,%2,%3}, {%4,%5,%6,%7}, {%8,%9}, {%0,%1,%2,%3};"
        : "+f"(d[0]), "+f"(d[1]), "+f"(d[2]), "+f"(d[3])
        : "r"(a[0]), "r"(a[1]), "r"(a[2]), "r"(a[3]), "r"(b0), "r"(b1));
}
#define LDSM_X4(r, addr)                                                        \
    asm volatile("ldmatrix.sync.aligned.m8n8.x4.shared.b16 {%0,%1,%2,%3}, [%4];"\
        : "=r"((r)[0]), "=r"((r)[1]), "=r"((r)[2]), "=r"((r)[3]) : "r"(addr))
#define LDSM_X4_T(r, addr)                                                      \
    asm volatile("ldmatrix.sync.aligned.m8n8.x4.trans.shared.b16 {%0,%1,%2,%3}, [%4];"\
        : "=r"((r)[0]), "=r"((r)[1]), "=r"((r)[2]), "=r"((r)[3]) : "r"(addr))

__device__ unsigned block_incl_scan(unsigned v, unsigned* wsum) {
    int lane = threadIdx.x & 31, wid = threadIdx.x >> 5;
#pragma unroll
    for (int d = 1; d < 32; d <<= 1) {
        unsigned n = __shfl_up_sync(0xffffffff, v, d);
        if (lane >= d) v += n;
    }
    if (lane == 31) wsum[wid] = v;
    __syncthreads();
    if (wid == 0) {
        unsigned w = wsum[lane];
#pragma unroll
        for (int d = 1; d < 32; d <<= 1) {
            unsigned n = __shfl_up_sync(0xffffffff, w, d);
            if (lane >= d) w += n;
        }
        wsum[lane] = w;
    }
    __syncthreads();
    return v + (wid > 0 ? wsum[wid - 1] : 0u);
}

// ===================== CSR build =============================
__global__ void count_kernel(const int* __restrict__ row,
                             const int* __restrict__ et, int E) {
    int e = blockIdx.x * blockDim.x + threadIdx.x;
    if (e >= E) return;
    int t = et[e];
    if (t == NET - 1) return;
    atomicAdd(&g_cnt[row[e] * NET + t], 1u);
}

// single-pass decoupled-lookback exclusive scan; also re-zeroes g_cnt
__global__ void __launch_bounds__(SCAN_BLK) scan_kernel(int nseg) {
    __shared__ unsigned wsum[32];
    __shared__ unsigned s_bid, s_total, s_prefix;
    int tid = threadIdx.x;
    if (tid == 0) s_bid = atomicAdd(&g_ticket, 1u);
    __syncthreads();
    unsigned bid = s_bid;
    int i = bid * SCAN_BLK + tid;
    unsigned v = (i < nseg) ? g_cnt[i] : 0u;
    if (i < nseg) g_cnt[i] = 0u;                 // restore for next replay
    unsigned incl = block_incl_scan(v, wsum);
    if (tid == SCAN_BLK - 1) s_total = incl;
    __syncthreads();
    if (tid == 0) {
        unsigned total = s_total;
        if (bid == 0) {
            atomicExch(&g_state[0], (2ULL << 32) | (unsigned long long)total);
            s_prefix = 0u;
        } else {
            atomicExch(&g_state[bid], (1ULL << 32) | (unsigned long long)total);
            unsigned running = 0u;
            int idx = (int)bid - 1;
            while (true) {
                unsigned long long s;
                do { s = atomicAdd(&g_state[idx], 0ULL); } while ((unsigned)(s >> 32) == 0u);
                running += (unsigned)s;
                if ((unsigned)(s >> 32) == 2u) break;
                --idx;
            }
            s_prefix = running;
            atomicExch(&g_state[bid], (2ULL << 32) | (unsigned long long)(running + total));
        }
    }
    __syncthreads();
    unsigned off = s_prefix + incl - v;
    if (i < nseg) {
        g_off[i] = off;
        g_cur[i] = off;
        if (i == nseg - 1) g_off[nseg] = off + v;
    }
}

// fill CSR edge list; also re-zeroes scan state for next replay
__global__ void fill_kernel(const int* __restrict__ row,
                            const int* __restrict__ col,
                            const int* __restrict__ et, int E) {
    int e = blockIdx.x * blockDim.x + threadIdx.x;
    if (e < 1024) g_state[e] = 0ULL;
    if (e == 0) g_ticket = 0u;
    if (e >= E) return;
    int t = et[e];
    if (t == NET - 1) return;
    int seg = row[e] * NET + t;
    unsigned pos = atomicAdd(&g_cur[seg], 1u);
    g_elist[pos] = col[e];
}

// ===================== fused aggregate + GEMM + stats ========
// CTA: 128 rows, 512 threads (16 warps, 4x4 grid of 32x32 output tiles).
// SMEM (uints): As[128][68], Bs[128][68] (both 272B rows: 16B-aligned for
// ldmatrix, start-bank step 4 -> conflict-free), selist[4096], soff[128*8],
// sstat[256 floats].
constexpr int APITCH = 68;       // uints per A row (136 halfs)
constexpr int BPITCH = 68;       // uints per B k-row (136 halfs)  [was 66: misaligned!]
constexpr int ECAP   = 4096;
constexpr int OFF_AS = 0;
constexpr int OFF_BS = OFF_AS + 128 * APITCH;      // 8704
constexpr int OFF_EL = OFF_BS + 128 * BPITCH;      // 17408
constexpr int OFF_SOFF = OFF_EL + ECAP;            // 21504
constexpr int OFF_STAT = OFF_SOFF + 128 * 8;       // 22528
constexpr int SMEM_UINTS = OFF_STAT + 2 * C;       // 22784
constexpr size_t FUSED_SMEM = (size_t)SMEM_UINTS * 4;   // 91136 B

__global__ void __launch_bounds__(512, 2)
fused_kernel(const float* __restrict__ x, const float* __restrict__ w,
             float* __restrict__ out, int nrows) {
    extern __shared__ uint32_t smu[];
    uint32_t* As = smu + OFF_AS;
    uint32_t* Bs = smu + OFF_BS;
    int*      selist = reinterpret_cast<int*>(smu + OFF_EL);
    unsigned* soff = smu + OFF_SOFF;
    float*    sstat = reinterpret_cast<float*>(smu + OFF_STAT);

    const int tid = threadIdx.x;
    const int wid = tid >> 5, lane = tid & 31;
    const int m0 = blockIdx.x * 128;
    const int rlim = min(128, nrows - m0);
    const float4* x4 = reinterpret_cast<const float4*>(x);
    const float4* w4 = reinterpret_cast<const float4*>(w);

    if (tid < 2 * C) sstat[tid] = 0.f;

    // ---- stage CTA segment offsets: soff[r][j] = g_off[(m0+r)*7 + j] ----
#pragma unroll
    for (int i = 0; i < 2; ++i) {
        int idx = tid + i * 512;                 // 0..1023
        int r = idx >> 3, j = idx & 7;
        soff[idx] = (r < rlim) ? g_off[(m0 + r) * NET + j] : 0u;
    }
    __syncthreads();
    const unsigned e0   = soff[0];               // CTA edge range start
    const unsigned etot = soff[(rlim - 1) * 8 + 7] - e0;
    // ---- stage edge list (coalesced); overflow falls back to global ----
    for (unsigned i = tid; i < min(etot, (unsigned)ECAP); i += 512)
        selist[i] = g_elist[e0 + i];
    __syncthreads();

    const int wm = (wid >> 2) * 32, wn = (wid & 3) * 32;
    const int gr = lane >> 2, gc = lane & 3;
    const int grp = lane >> 3, rr = lane & 7;

    // ldmatrix per-thread smem byte addresses
    const uint32_t sbase = smem_u32(smu);
    const uint32_t abase = sbase + OFF_AS * 4;
    const uint32_t bbase = sbase + OFF_BS * 4;
    // A (non-trans): m0..m3 = {rows wm+(grp&1)*8+rr, k halves (grp>>1)*8}
    uint32_t aadr0 = abase + (wm + (grp & 1) * 8 + rr) * APITCH * 4 + (grp >> 1) * 16;
    uint32_t aadr1 = aadr0 + 16 * APITCH * 4;
    // B (trans): m0..m3 = {k rows (grp&1)*8+rr, n cols wn+(grp>>1)*8}
    uint32_t badr0 = bbase + ((grp & 1) * 8 + rr) * BPITCH * 4 + (wn + (grp >> 1) * 8) * 2;
    uint32_t badr1 = badr0 + 16 * 2;             // +16 n cols

    float acc[2][4][4];
#pragma unroll
    for (int f = 0; f < 2; ++f)
#pragma unroll
        for (int g = 0; g < 4; ++g)
#pragma unroll
            for (int q = 0; q < 4; ++q) acc[f][g][q] = 0.f;

    for (int t = 0; t < NET; ++t) {
        // ---- B_t: W[t*128+k][n] -> Bs[k][n] fp16, natural K x N layout ----
#pragma unroll
        for (int i = 0; i < 8; ++i) {
            int e = tid + i * 512;               // 0..4095
            int k = e >> 5, n4 = e & 31;
            float4 v = w4[(size_t)(t * C + k) * 32 + n4];
            *reinterpret_cast<uint2*>(&Bs[k * BPITCH + n4 * 2]) =
                make_uint2(pack_h2(v.x, v.y), pack_h2(v.z, v.w));
        }
        // ---- A_t: gather-mean, warp-per-row (8 rows/warp) ----
#pragma unroll
        for (int i = 0; i < 8; ++i) {
            int r = wid * 8 + i;
            float4 val = make_float4(0.f, 0.f, 0.f, 0.f);
            if (r < rlim) {
                if (t == NET - 1) {
                    val = x4[(size_t)(m0 + r) * 32 + lane];      // self slot
                } else {
                    unsigned beg = soff[r * 8 + t] - e0;
                    unsigned end = soff[r * 8 + t + 1] - e0;
                    for (unsigned e = beg; e < end; ++e) {
                        int c = (e < (unsigned)ECAP) ? selist[e] : g_elist[e0 + e];
                        float4 v = x4[(size_t)c * 32 + lane];
                        val.x += v.x; val.y += v.y; val.z += v.z; val.w += v.w;
                    }
                    if (end > beg) {
                        float inv = 1.0f / (float)(end - beg);
                        val.x *= inv; val.y *= inv; val.z *= inv; val.w *= inv;
                    }
                }
            }
            *reinterpret_cast<uint2*>(&As[r * APITCH + 2 * lane]) =
                make_uint2(pack_h2(val.x, val.y), pack_h2(val.z, val.w));
        }
        __syncthreads();
        // ---- MMA: 8 k16-steps, ldmatrix operands ----
#pragma unroll
        for (int ks = 0; ks < 8; ++ks) {
            uint32_t af0[4], af1[4], bf0[4], bf1[4];
            LDSM_X4(af0, aadr0 + ks * 32);                     // +16 halfs per ks
            LDSM_X4(af1, aadr1 + ks * 32);
            LDSM_X4_T(bf0, badr0 + ks * 16 * BPITCH * 4);      // +16 k-rows per ks
            LDSM_X4_T(bf1, badr1 + ks * 16 * BPITCH * 4);
            mma_f16(acc[0][0], af0, bf0[0], bf0[1]);
            mma_f16(acc[0][1], af0, bf0[2], bf0[3]);
            mma_f16(acc[0][2], af0, bf1[0], bf1[1]);
            mma_f16(acc[0][3], af0, bf1[2], bf1[3]);
            mma_f16(acc[1][0], af1, bf0[0], bf0[1]);
            mma_f16(acc[1][1], af1, bf0[2], bf0[3]);
            mma_f16(acc[1][2], af1, bf1[0], bf1[1]);
            mma_f16(acc[1][3], af1, bf1[2], bf1[3]);
        }
        __syncthreads();   // before next t overwrites As/Bs
    }

    // ---- epilogue: write out once + fused BN stats ----
#pragma unroll
    for (int f = 0; f < 2; ++f) {
        int r0 = m0 + wm + 16 * f + gr;
#pragma unroll
        for (int g = 0; g < 4; ++g) {
            int cn = wn + 8 * g + gc * 2;
            float s0 = 0.f, q0 = 0.f, s1 = 0.f, q1 = 0.f;
            if (r0 < nrows) {
                float v0 = acc[f][g][0], v1 = acc[f][g][1];
                *reinterpret_cast<float2*>(&out[(size_t)r0 * C + cn]) = make_float2(v0, v1);
                s0 += v0; q0 += v0 * v0; s1 += v1; q1 += v1 * v1;
            }
            if (r0 + 8 < nrows) {
                float v0 = acc[f][g][2], v1 = acc[f][g][3];
                *reinterpret_cast<float2*>(&out[(size_t)(r0 + 8) * C + cn]) = make_float2(v0, v1);
                s0 += v0; q0 += v0 * v0; s1 += v1; q1 += v1 * v1;
            }
            atomicAdd(&sstat[cn], s0);
            atomicAdd(&sstat[C + cn], q0);
            atomicAdd(&sstat[cn + 1], s1);
            atomicAdd(&sstat[C + cn + 1], q1);
        }
    }
    __syncthreads();
    if (tid < 2 * C) atomicAdd(&g_stats[tid], sstat[tid]);
}

// ===================== BN finalize + normalize ===============
__global__ void bnfin_kernel(const float* __restrict__ gamma, const float* __restrict__ beta,
                             float inv_n) {
    int c = threadIdx.x;
    float mean = g_stats[c] * inv_n;
    float var  = g_stats[C + c] * inv_n - mean * mean;
    float sc   = gamma[c] * rsqrtf(var + 1e-5f);
    g_scale[c] = sc;
    g_shift[c] = beta[c] - mean * sc;
    g_stats[c] = 0.f;                 // restore for next replay
    g_stats[C + c] = 0.f;
}

__global__ void norm_kernel(float* __restrict__ out, size_t n4) {
    size_t i = (size_t)blockIdx.x * blockDim.x + threadIdx.x;
    size_t stride = (size_t)gridDim.x * blockDim.x;
    const float4* sc4 = reinterpret_cast<const float4*>(g_scale);
    const float4* sh4 = reinterpret_cast<const float4*>(g_shift);
    float4* o4 = reinterpret_cast<float4*>(out);
    for (size_t j = i; j < n4; j += stride) {
        int c4 = (int)(j & 31);
        float4 v = o4[j];
        float4 a = sc4[c4], b = sh4[c4];
        v.x = v.x * a.x + b.x;
        v.y = v.y * a.y + b.y;
        v.z = v.z * a.z + b.z;
        v.w = v.w * a.w + b.w;
        o4[j] = v;
    }
}

// ===================== launch ================================
extern "C" void kernel_launch(void* const* d_in, const int* in_sizes, int n_in,
                              void* d_out, int out_size) {
    const float* x     = (const float*)d_in[0];
    const int*   row   = (const int*)d_in[1];   // JAX x64-disabled: int32
    const int*   col   = (const int*)d_in[2];
    const int*   et    = (const int*)d_in[3];
    const float* w     = (const float*)d_in[4];
    const float* gamma = (const float*)d_in[5];
    const float* beta  = (const float*)d_in[6];
    float* out = (float*)d_out;

    int nrows = in_sizes[0] / C;          // 100000
    int E     = in_sizes[1];              // 700000
    int nseg  = nrows * NET;
    int nblk  = (nseg + SCAN_BLK - 1) / SCAN_BLK;

    cudaFuncSetAttribute(fused_kernel, cudaFuncAttributeMaxDynamicSharedMemorySize,
                         (int)FUSED_SMEM);

    count_kernel<<<(E + 255) / 256, 256>>>(row, et, E);                         // 0
    scan_kernel<<<nblk, SCAN_BLK>>>(nseg);                                      // 1
    fill_kernel<<<(E + 255) / 256, 256>>>(row, col, et, E);                     // 2
    fused_kernel<<<(nrows + 127) / 128, 512, FUSED_SMEM>>>(x, w, out, nrows);   // 3 <- profiled
    bnfin_kernel<<<1, 128>>>(gamma, beta, 1.0f / (float)nrows);                 // 4
    norm_kernel<<<2048, 256>>>(out, (size_t)nrows * 32);                        // 5
}